// round 9
// baseline (speedup 1.0000x reference)
#include <cuda_runtime.h>
#include <math.h>

#define STATE_DIM 64
#define HID 512
#define ACT 8
#define BATCH 128
#define SEQ 16
#define TSTEPS (SEQ*BATCH)   // 2048 sequential LSTM steps
#define G4 (4*HID)
#define N0 64
#define N1 64
#define NCTA (N0+N1)
#define SENT 0x7FBFFFFFu     // NaN payload: impossible h bit pattern
#define FULLM 0xffffffffu

// ---------------- scratch ---------------------------------------------------
__device__ float g_x [BATCH*HID];
__device__ float g_A0[BATCH*G4];
__device__ float g_h0[TSTEPS*HID];
__device__ float g_h1[TSTEPS*HID];

// ---------------- helpers ---------------------------------------------------
__device__ __forceinline__ float tanhapx(float x) {
    float y; asm("tanh.approx.f32 %0, %1;" : "=f"(y) : "f"(x)); return y;
}
__device__ __forceinline__ float sigf(float x) { return 0.5f*tanhapx(0.5f*x) + 0.5f; }

__device__ __forceinline__ unsigned ldvol32(const unsigned* p) {
    unsigned v;
    asm volatile("ld.volatile.global.u32 %0, [%1];" : "=r"(v) : "l"(p) : "memory");
    return v;
}
__device__ __forceinline__ uint2 ldvol64(const uint2* p) {
    uint2 v;
    asm volatile("ld.volatile.global.v2.u32 {%0,%1}, [%2];"
                 : "=r"(v.x), "=r"(v.y) : "l"(p) : "memory");
    return v;
}
__device__ __forceinline__ void stvolf(float* p, float v) {
    asm volatile("st.volatile.global.f32 [%0], %1;" :: "l"(p), "f"(v) : "memory");
}
__device__ __forceinline__ unsigned long long pk2(uint2 v) {
    unsigned long long r;
    asm("mov.b64 %0, {%1,%2};" : "=l"(r) : "r"(v.x), "r"(v.y));
    return r;
}
__device__ __forceinline__ unsigned long long fma2(unsigned long long a,
                                                   unsigned long long b,
                                                   unsigned long long c) {
    unsigned long long d;
    asm("fma.rn.f32x2 %0, %1, %2, %3;" : "=l"(d) : "l"(a), "l"(b), "l"(c));
    return d;
}
__device__ __forceinline__ float fsum(unsigned long long v) {
    float x, y;
    asm("mov.b64 {%0,%1}, %2;" : "=f"(x), "=f"(y) : "l"(v));
    return x + y;
}

// ---------------- K0: sentinel-fill h histories (graph replays) -------------
__global__ void k_init() {
    unsigned i = blockIdx.x*blockDim.x + threadIdx.x;   // 1024*256 = 262144
    uint4 s = make_uint4(SENT, SENT, SENT, SENT);
    ((uint4*)g_h0)[i] = s;
    ((uint4*)g_h1)[i] = s;
}

// ---------------- K1: LayerNorm + pre-linear --------------------------------
__global__ void k_pre(const float* __restrict__ state, const float* __restrict__ lng,
                      const float* __restrict__ lnb,   const float* __restrict__ Wpre,
                      const float* __restrict__ bpre) {
    __shared__ float xn[STATE_DIM];
    __shared__ float stats[2];
    int b = blockIdx.x, tid = threadIdx.x;
    if (tid < STATE_DIM) xn[tid] = state[b*STATE_DIM + tid];
    __syncthreads();
    if (tid == 0) {
        float mu = 0.f;
        for (int k = 0; k < STATE_DIM; k++) mu += xn[k];
        mu *= (1.f/STATE_DIM);
        float var = 0.f;
        for (int k = 0; k < STATE_DIM; k++) { float d = xn[k]-mu; var += d*d; }
        var *= (1.f/STATE_DIM);
        stats[0] = mu; stats[1] = rsqrtf(var + 1e-5f);
    }
    __syncthreads();
    float mu = stats[0], rs = stats[1];
    if (tid < STATE_DIM) xn[tid] = (xn[tid]-mu)*rs*lng[tid] + lnb[tid];
    __syncthreads();
    float acc = bpre[tid];
    const float* w = Wpre + tid*STATE_DIM;
    #pragma unroll 16
    for (int k = 0; k < STATE_DIM; k++) acc = fmaf(w[k], xn[k], acc);
    g_x[b*HID + tid] = acc;
}

// ---------------- K2: A0 = W_ih0@x + b_ih0 + b_hh0 --------------------------
__global__ void k_a0(const float* __restrict__ Wih, const float* __restrict__ bih,
                     const float* __restrict__ bhh) {
    int tid = threadIdx.x, lane = tid & 31, warp = tid >> 5;
    int row = blockIdx.x*8 + warp;
    float wr[16];
    const float* w = Wih + (size_t)row*HID + lane*16;
    #pragma unroll
    for (int i = 0; i < 16; i++) wr[i] = w[i];
    float bsum = bih[row] + bhh[row];
    __shared__ float xs[HID];
    for (int b = 0; b < BATCH; b++) {
        __syncthreads();
        for (int i = tid; i < HID; i += 256) xs[i] = g_x[b*HID + i];
        __syncthreads();
        float a = 0.f;
        #pragma unroll
        for (int i = 0; i < 16; i++) a = fmaf(wr[i], xs[lane*16 + i], a);
        #pragma unroll
        for (int o = 16; o > 0; o >>= 1) a += __shfl_xor_sync(FULLM, a, o);
        if (lane == 0) g_A0[b*G4 + row] = a + bsum;
    }
}

// ---------------- K_LSTM: warp-autonomous outputs, zero barriers ------------
// 8 warps/CTA; warp owns one output j (4 gate rows, all cols in registers).
// Lane l handles column pairs {2l+64k}. Probe-then-bulk sentinel polling.
// In-warp butterfly reduce; all lanes replicate c_state; lane0 stores 1 float.
__global__ void __launch_bounds__(256, 1)
k_lstm(const float* __restrict__ Wih, const float* __restrict__ Whh,
       const float* __restrict__ bih, const float* __restrict__ bhh) {
    __shared__ float4 As4[BATCH*8];   // layer-0: (i,f,g,o) per (batch, local out)
    const int tid = threadIdx.x, lane = tid & 31, warp = tid >> 5;

    if (blockIdx.x < N0) {
        // ===================== layer-0 group =====================
        const int g = blockIdx.x;
        const int j = g*8 + warp;
        unsigned long long w2[4][8];   // gate x k ; cols 2l+64k of Whh0 row
        #pragma unroll
        for (int gt = 0; gt < 4; gt++) {
            const float* wr = Whh + (size_t)(gt*HID + j)*HID + 2*lane;
            #pragma unroll
            for (int k = 0; k < 8; k++)
                w2[gt][k] = *(const unsigned long long*)(wr + 64*k);
        }
        for (int i = tid; i < BATCH*8; i += 256) {
            int b = i >> 3, jj = i & 7;
            As4[i] = make_float4(g_A0[b*G4 + 0*HID + g*8 + jj],
                                 g_A0[b*G4 + 1*HID + g*8 + jj],
                                 g_A0[b*G4 + 2*HID + g*8 + jj],
                                 g_A0[b*G4 + 3*HID + g*8 + jj]);
        }
        __syncthreads();

        float c_state = 0.f;
        for (int t = 0; t < TSTEPS; t++) {
            unsigned long long h[8];
            if (t > 0) {
                const float* hs = g_h0 + (size_t)(t-1)*HID;
                // probe one word (col 2l), spin narrow
                {
                    const unsigned* pr = (const unsigned*)hs + 2*lane;
                    unsigned v = ldvol32(pr);
                    while (__any_sync(FULLM, v == SENT)) v = ldvol32(pr);
                }
                // bulk load + verify
                int bad;
                do {
                    bad = 0;
                    #pragma unroll
                    for (int k = 0; k < 8; k++) {
                        uint2 v = ldvol64((const uint2*)(hs + 2*lane + 64*k));
                        bad |= (v.x == SENT) | (v.y == SENT);
                        h[k] = pk2(v);
                    }
                } while (__any_sync(FULLM, bad));
            } else {
                #pragma unroll
                for (int k = 0; k < 8; k++) h[k] = 0ull;
            }
            unsigned long long a0=0ull, a1=0ull, a2=0ull, a3=0ull;
            #pragma unroll
            for (int k = 0; k < 8; k++) {
                a0 = fma2(w2[0][k], h[k], a0);
                a1 = fma2(w2[1][k], h[k], a1);
                a2 = fma2(w2[2][k], h[k], a2);
                a3 = fma2(w2[3][k], h[k], a3);
            }
            float pi = fsum(a0), pf = fsum(a1), pg = fsum(a2), po = fsum(a3);
            #pragma unroll
            for (int o = 16; o > 0; o >>= 1) {
                pi += __shfl_xor_sync(FULLM, pi, o);
                pf += __shfl_xor_sync(FULLM, pf, o);
                pg += __shfl_xor_sync(FULLM, pg, o);
                po += __shfl_xor_sync(FULLM, po, o);
            }
            float4 A = As4[(t & (BATCH-1))*8 + warp];
            pi += A.x; pf += A.y; pg += A.z; po += A.w;
            c_state = sigf(pf)*c_state + sigf(pi)*tanhapx(pg);
            float hv = sigf(po)*tanhapx(c_state);
            if (lane == 0) stvolf(g_h0 + (size_t)t*HID + j, hv);
        }
    } else {
        // ===================== layer-1 group =====================
        const int g = blockIdx.x - N0;
        const int j = g*8 + warp;
        unsigned long long w2[4][16];  // cols 2l+64k of [Wih1 row | Whh1 row]
        #pragma unroll
        for (int gt = 0; gt < 4; gt++) {
            const float* wi = Wih + (size_t)G4*HID + (size_t)(gt*HID + j)*HID + 2*lane;
            const float* wh = Whh + (size_t)G4*HID + (size_t)(gt*HID + j)*HID + 2*lane;
            #pragma unroll
            for (int k = 0; k < 8; k++) {
                w2[gt][k]     = *(const unsigned long long*)(wi + 64*k);
                w2[gt][k+8]   = *(const unsigned long long*)(wh + 64*k);
            }
        }
        float bi = bih[G4 + 0*HID + j] + bhh[G4 + 0*HID + j];
        float bf = bih[G4 + 1*HID + j] + bhh[G4 + 1*HID + j];
        float bg = bih[G4 + 2*HID + j] + bhh[G4 + 2*HID + j];
        float bo = bih[G4 + 3*HID + j] + bhh[G4 + 3*HID + j];

        float c_state = 0.f;
        for (int t = 0; t < TSTEPS; t++) {
            unsigned long long h[16];
            const float* h0s = g_h0 + (size_t)t*HID;
            if (t > 0) {
                const float* h1s = g_h1 + (size_t)(t-1)*HID;
                // probe one h1 word (the recurrence laggard)
                {
                    const unsigned* pr = (const unsigned*)h1s + 2*lane;
                    unsigned v = ldvol32(pr);
                    while (__any_sync(FULLM, v == SENT)) v = ldvol32(pr);
                }
                int bad;
                do {
                    bad = 0;
                    #pragma unroll
                    for (int k = 0; k < 8; k++) {
                        uint2 v = ldvol64((const uint2*)(h0s + 2*lane + 64*k));
                        bad |= (v.x == SENT) | (v.y == SENT);
                        h[k] = pk2(v);
                    }
                    #pragma unroll
                    for (int k = 0; k < 8; k++) {
                        uint2 v = ldvol64((const uint2*)(h1s + 2*lane + 64*k));
                        bad |= (v.x == SENT) | (v.y == SENT);
                        h[k+8] = pk2(v);
                    }
                } while (__any_sync(FULLM, bad));
            } else {
                // h1[-1] = 0; still must wait for h0[0]
                {
                    const unsigned* pr = (const unsigned*)h0s + 2*lane;
                    unsigned v = ldvol32(pr);
                    while (__any_sync(FULLM, v == SENT)) v = ldvol32(pr);
                }
                int bad;
                do {
                    bad = 0;
                    #pragma unroll
                    for (int k = 0; k < 8; k++) {
                        uint2 v = ldvol64((const uint2*)(h0s + 2*lane + 64*k));
                        bad |= (v.x == SENT) | (v.y == SENT);
                        h[k] = pk2(v);
                    }
                } while (__any_sync(FULLM, bad));
                #pragma unroll
                for (int k = 8; k < 16; k++) h[k] = 0ull;
            }
            unsigned long long a0=0ull, a1=0ull, a2=0ull, a3=0ull;
            #pragma unroll
            for (int k = 0; k < 16; k++) {
                a0 = fma2(w2[0][k], h[k], a0);
                a1 = fma2(w2[1][k], h[k], a1);
                a2 = fma2(w2[2][k], h[k], a2);
                a3 = fma2(w2[3][k], h[k], a3);
            }
            float pi = fsum(a0), pf = fsum(a1), pg = fsum(a2), po = fsum(a3);
            #pragma unroll
            for (int o = 16; o > 0; o >>= 1) {
                pi += __shfl_xor_sync(FULLM, pi, o);
                pf += __shfl_xor_sync(FULLM, pf, o);
                pg += __shfl_xor_sync(FULLM, pg, o);
                po += __shfl_xor_sync(FULLM, po, o);
            }
            pi += bi; pf += bf; pg += bg; po += bo;
            c_state = sigf(pf)*c_state + sigf(pi)*tanhapx(pg);
            float hv = sigf(po)*tanhapx(c_state);
            if (lane == 0) stvolf(g_h1 + (size_t)t*HID + j, hv);
        }
    }
}

// ---------------- K3: final FC + tanh ---------------------------------------
__global__ void k_fc(const float* __restrict__ Wfc, const float* __restrict__ bfc,
                     float* __restrict__ out) {
    int s = blockIdx.x;
    int tid = threadIdx.x, lane = tid & 31, a = tid >> 5;
    int tt = s >> 7, b = s & 127;
    const float* h = g_h1 + (size_t)s*HID;
    const float* w = Wfc + a*HID;
    float acc = 0.f;
    for (int k = lane; k < HID; k += 32) acc = fmaf(h[k], w[k], acc);
    #pragma unroll
    for (int o = 16; o > 0; o >>= 1) acc += __shfl_xor_sync(FULLM, acc, o);
    if (lane == 0) out[b*(SEQ*ACT) + tt*ACT + a] = tanhf(acc + bfc[a]);
}

// ---------------------------------------------------------------------------
extern "C" void kernel_launch(void* const* d_in, const int* in_sizes, int n_in,
                              void* d_out, int out_size) {
    const float* state = (const float*)d_in[0];
    const float* lng   = (const float*)d_in[1];
    const float* lnb   = (const float*)d_in[2];
    const float* Wpre  = (const float*)d_in[3];
    const float* bpre  = (const float*)d_in[4];
    const float* Wih   = (const float*)d_in[5];
    const float* Whh   = (const float*)d_in[6];
    const float* bih   = (const float*)d_in[7];
    const float* bhh   = (const float*)d_in[8];
    const float* Wfc   = (const float*)d_in[9];
    const float* bfc   = (const float*)d_in[10];
    float* out = (float*)d_out;

    k_init<<<1024, 256>>>();
    k_pre <<<BATCH, 512>>>(state, lng, lnb, Wpre, bpre);
    k_a0  <<<G4/8, 256>>>(Wih, bih, bhh);
    k_lstm<<<NCTA, 256>>>(Wih, Whh, bih, bhh);
    k_fc  <<<TSTEPS, 256>>>(Wfc, bfc, out);
}

// round 10
// speedup vs baseline: 4.9725x; 4.9725x over previous
#include <cuda_runtime.h>
#include <math.h>

#define STATE_DIM 64
#define HID 512
#define ACT 8
#define BATCH 128
#define SEQ 16
#define TSTEPS (SEQ*BATCH)   // 2048 sequential LSTM steps
#define G4 (4*HID)
#define N0 64
#define N1 64
#define NCTA (N0+N1)
#define TPB 512
#define SENT 0x7FBFFFFFu     // NaN payload: impossible h bit pattern
#define FULLM 0xffffffffu

// ---------------- scratch ---------------------------------------------------
__device__ float g_x [BATCH*HID];
__device__ float g_A0[BATCH*G4];
__device__ float g_h0[TSTEPS*HID];
__device__ float g_h1[TSTEPS*HID];

// ---------------- helpers ---------------------------------------------------
__device__ __forceinline__ float tanhapx(float x) {
    float y; asm("tanh.approx.f32 %0, %1;" : "=f"(y) : "f"(x)); return y;
}
__device__ __forceinline__ float sigf(float x) { return 0.5f*tanhapx(0.5f*x) + 0.5f; }

__device__ __forceinline__ unsigned ldvol32(const unsigned* p) {
    unsigned v;
    asm volatile("ld.volatile.global.u32 %0, [%1];" : "=r"(v) : "l"(p) : "memory");
    return v;
}
__device__ __forceinline__ uint2 ldvol64(const uint2* p) {
    uint2 v;
    asm volatile("ld.volatile.global.v2.u32 {%0,%1}, [%2];"
                 : "=r"(v.x), "=r"(v.y) : "l"(p) : "memory");
    return v;
}
__device__ __forceinline__ void stvolf(float* p, float v) {
    asm volatile("st.volatile.global.f32 [%0], %1;" :: "l"(p), "f"(v) : "memory");
}
__device__ __forceinline__ unsigned long long fma2(unsigned long long a,
                                                   unsigned long long b,
                                                   unsigned long long c) {
    unsigned long long d;
    asm("fma.rn.f32x2 %0, %1, %2, %3;" : "=l"(d) : "l"(a), "l"(b), "l"(c));
    return d;
}
__device__ __forceinline__ float fsum(unsigned long long v) {
    float x, y;
    asm("mov.b64 {%0,%1}, %2;" : "=f"(x), "=f"(y) : "l"(v));
    return x + y;
}

// ---------------- K0: sentinel-fill h histories (graph replays) -------------
__global__ void k_init() {
    unsigned i = blockIdx.x*blockDim.x + threadIdx.x;   // 1024*256 = 262144
    uint4 s = make_uint4(SENT, SENT, SENT, SENT);
    ((uint4*)g_h0)[i] = s;
    ((uint4*)g_h1)[i] = s;
}

// ---------------- K1: LayerNorm + pre-linear --------------------------------
__global__ void k_pre(const float* __restrict__ state, const float* __restrict__ lng,
                      const float* __restrict__ lnb,   const float* __restrict__ Wpre,
                      const float* __restrict__ bpre) {
    __shared__ float xn[STATE_DIM];
    __shared__ float stats[2];
    int b = blockIdx.x, tid = threadIdx.x;
    if (tid < STATE_DIM) xn[tid] = state[b*STATE_DIM + tid];
    __syncthreads();
    if (tid == 0) {
        float mu = 0.f;
        for (int k = 0; k < STATE_DIM; k++) mu += xn[k];
        mu *= (1.f/STATE_DIM);
        float var = 0.f;
        for (int k = 0; k < STATE_DIM; k++) { float d = xn[k]-mu; var += d*d; }
        var *= (1.f/STATE_DIM);
        stats[0] = mu; stats[1] = rsqrtf(var + 1e-5f);
    }
    __syncthreads();
    float mu = stats[0], rs = stats[1];
    if (tid < STATE_DIM) xn[tid] = (xn[tid]-mu)*rs*lng[tid] + lnb[tid];
    __syncthreads();
    float acc = bpre[tid];
    const float* w = Wpre + tid*STATE_DIM;
    #pragma unroll 16
    for (int k = 0; k < STATE_DIM; k++) acc = fmaf(w[k], xn[k], acc);
    g_x[b*HID + tid] = acc;
}

// ---------------- K2: A0 = W_ih0@x + b_ih0 + b_hh0 --------------------------
__global__ void k_a0(const float* __restrict__ Wih, const float* __restrict__ bih,
                     const float* __restrict__ bhh) {
    int tid = threadIdx.x, lane = tid & 31, warp = tid >> 5;
    int row = blockIdx.x*8 + warp;
    float wr[16];
    const float* w = Wih + (size_t)row*HID + lane*16;
    #pragma unroll
    for (int i = 0; i < 16; i++) wr[i] = w[i];
    float bsum = bih[row] + bhh[row];
    __shared__ float xs[HID];
    for (int b = 0; b < BATCH; b++) {
        __syncthreads();
        for (int i = tid; i < HID; i += 256) xs[i] = g_x[b*HID + i];
        __syncthreads();
        float a = 0.f;
        #pragma unroll
        for (int i = 0; i < 16; i++) a = fmaf(wr[i], xs[lane*16 + i], a);
        #pragma unroll
        for (int o = 16; o > 0; o >>= 1) a += __shfl_xor_sync(FULLM, a, o);
        if (lane == 0) g_A0[b*G4 + row] = a + bsum;
    }
}

// ---------------- K_LSTM: R8 skeleton + atomic-smem reduce + fast tail ------
// Each compute warp polls+stages its own h slice (sentinel dataflow), FFMA2,
// then atomicAdd's its partial into a parity-buffered 32-word accumulator
// (pre-seeded with the A0/bias term). One __syncthreads per step; warp 0's
// tail is 1 LDS + 1 MUFU + 4 shfl + cell.
__global__ void __launch_bounds__(TPB, 1)
k_lstm(const float* __restrict__ Wih, const float* __restrict__ Whh,
       const float* __restrict__ bih, const float* __restrict__ bhh) {
    __shared__ float hbuf[2*HID];
    __shared__ float acc[2][32];
    __shared__ float As[BATCH*32];
    __shared__ float bias1[32];
    const int tid = threadIdx.x, lane = tid & 31, warp = tid >> 5;
    const int j = lane & 7;
    float c_state = 0.f;

    if (blockIdx.x < N0) {
        // ===================== layer-0 group =====================
        const int g = blockIdx.x;
        const int grow = (lane>>3)*HID + g*8 + j;
        unsigned long long w2[16];                 // 32 cols [warp*32,+32)
        {
            const ulonglong2* wp = (const ulonglong2*)(Whh + (size_t)grow*HID + warp*32);
            #pragma unroll
            for (int i = 0; i < 8; i++) { ulonglong2 v = wp[i]; w2[2*i] = v.x; w2[2*i+1] = v.y; }
        }
        for (int i = tid; i < BATCH*32; i += TPB) {
            int bb = i >> 5, lr = i & 31;
            As[i] = g_A0[bb*G4 + (lr>>3)*HID + g*8 + (lr&7)];
        }
        __syncthreads();
        if (tid < 32) { acc[0][tid] = As[0*32 + tid]; acc[1][tid] = As[1*32 + tid]; }
        __syncthreads();

        for (int t = 0; t < TSTEPS; t++) {
            const int par = t & 1;
            if (t > 0) {
                const unsigned* p =
                    (const unsigned*)(g_h0 + (size_t)(t-1)*HID + warp*32) + lane;
                unsigned v = ldvol32(p);
                while (!__all_sync(FULLM, v != SENT)) v = ldvol32(p);
                hbuf[warp*32 + lane] = __uint_as_float(v);
            } else {
                hbuf[warp*32 + lane] = 0.f;
            }
            __syncwarp();
            unsigned long long a0 = 0ull, a1 = 0ull;
            const ulonglong2* hp2 = (const ulonglong2*)(hbuf + warp*32);
            #pragma unroll
            for (int i = 0; i < 8; i++) {
                ulonglong2 v = hp2[i];
                a0 = fma2(w2[2*i],   v.x, a0);
                a1 = fma2(w2[2*i+1], v.y, a1);
            }
            atomicAdd(&acc[par][lane], fsum(a0) + fsum(a1));
            __syncthreads();                                      // barB
            if (warp == 0) {
                float gv = acc[par][lane];
                acc[par][lane] = As[(((t+2) & (BATCH-1)))*32 + lane];  // reseed t+2
                float act = (lane >= 16 && lane < 24) ? tanhapx(gv) : sigf(gv);
                float vi = __shfl_sync(FULLM, act, j);
                float vf = __shfl_sync(FULLM, act, 8 + j);
                float vg = __shfl_sync(FULLM, act, 16 + j);
                float vo = __shfl_sync(FULLM, act, 24 + j);
                c_state = vf*c_state + vi*vg;
                float hv = vo*tanhapx(c_state);
                if (lane < 8) stvolf(g_h0 + (size_t)t*HID + g*8 + lane, hv);
            }
        }
    } else {
        // ===================== layer-1 group =====================
        const int g = blockIdx.x - N0;
        const int grow = (lane>>3)*HID + g*8 + j;
        unsigned long long w2[32];                 // 64 cols [warp*64,+64) of [h0|h1]
        {
            const ulonglong2* wp = (warp < 8)
                ? (const ulonglong2*)(Wih + (size_t)G4*HID + (size_t)grow*HID + warp*64)
                : (const ulonglong2*)(Whh + (size_t)G4*HID + (size_t)grow*HID + (warp-8)*64);
            #pragma unroll
            for (int i = 0; i < 16; i++) { ulonglong2 v = wp[i]; w2[2*i] = v.x; w2[2*i+1] = v.y; }
        }
        if (tid < 32) {
            float bv = bih[G4 + (tid>>3)*HID + g*8 + (tid&7)]
                     + bhh[G4 + (tid>>3)*HID + g*8 + (tid&7)];
            bias1[tid] = bv;
            acc[0][tid] = bv;
            acc[1][tid] = bv;
        }
        __syncthreads();

        for (int t = 0; t < TSTEPS; t++) {
            const int par = t & 1;
            if (warp < 8) {                        // h0[t]: produced ahead, cheap poll
                const uint2* p =
                    (const uint2*)(g_h0 + (size_t)t*HID + warp*64) + lane;
                uint2 v = ldvol64(p);
                while (!__all_sync(FULLM, (v.x != SENT) & (v.y != SENT)))
                    v = ldvol64(p);
                *(float2*)(hbuf + warp*64 + 2*lane) =
                    make_float2(__uint_as_float(v.x), __uint_as_float(v.y));
            } else if (t > 0) {                    // h1[t-1]: the recurrence
                const uint2* p =
                    (const uint2*)(g_h1 + (size_t)(t-1)*HID + (warp-8)*64) + lane;
                uint2 v = ldvol64(p);
                while (!__all_sync(FULLM, (v.x != SENT) & (v.y != SENT)))
                    v = ldvol64(p);
                *(float2*)(hbuf + warp*64 + 2*lane) =
                    make_float2(__uint_as_float(v.x), __uint_as_float(v.y));
            } else {
                *(float2*)(hbuf + warp*64 + 2*lane) = make_float2(0.f, 0.f);
            }
            __syncwarp();
            unsigned long long a0 = 0ull, a1 = 0ull, a2 = 0ull, a3 = 0ull;
            const ulonglong2* hp2 = (const ulonglong2*)(hbuf + warp*64);
            #pragma unroll
            for (int i = 0; i < 8; i++) {
                ulonglong2 v0 = hp2[2*i], v1 = hp2[2*i+1];
                a0 = fma2(w2[4*i],   v0.x, a0);
                a1 = fma2(w2[4*i+1], v0.y, a1);
                a2 = fma2(w2[4*i+2], v1.x, a2);
                a3 = fma2(w2[4*i+3], v1.y, a3);
            }
            atomicAdd(&acc[par][lane], (fsum(a0) + fsum(a1)) + (fsum(a2) + fsum(a3)));
            __syncthreads();                                      // barB
            if (warp == 0) {
                float gv = acc[par][lane];
                acc[par][lane] = bias1[lane];                     // reseed t+2
                float act = (lane >= 16 && lane < 24) ? tanhapx(gv) : sigf(gv);
                float vi = __shfl_sync(FULLM, act, j);
                float vf = __shfl_sync(FULLM, act, 8 + j);
                float vg = __shfl_sync(FULLM, act, 16 + j);
                float vo = __shfl_sync(FULLM, act, 24 + j);
                c_state = vf*c_state + vi*vg;
                float hv = vo*tanhapx(c_state);
                if (lane < 8) stvolf(g_h1 + (size_t)t*HID + g*8 + lane, hv);
            }
        }
    }
}

// ---------------- K3: final FC + tanh ---------------------------------------
__global__ void k_fc(const float* __restrict__ Wfc, const float* __restrict__ bfc,
                     float* __restrict__ out) {
    int s = blockIdx.x;
    int tid = threadIdx.x, lane = tid & 31, a = tid >> 5;
    int tt = s >> 7, b = s & 127;
    const float* h = g_h1 + (size_t)s*HID;
    const float* w = Wfc + a*HID;
    float acc = 0.f;
    for (int k = lane; k < HID; k += 32) acc = fmaf(h[k], w[k], acc);
    #pragma unroll
    for (int o = 16; o > 0; o >>= 1) acc += __shfl_xor_sync(FULLM, acc, o);
    if (lane == 0) out[b*(SEQ*ACT) + tt*ACT + a] = tanhf(acc + bfc[a]);
}

// ---------------------------------------------------------------------------
extern "C" void kernel_launch(void* const* d_in, const int* in_sizes, int n_in,
                              void* d_out, int out_size) {
    const float* state = (const float*)d_in[0];
    const float* lng   = (const float*)d_in[1];
    const float* lnb   = (const float*)d_in[2];
    const float* Wpre  = (const float*)d_in[3];
    const float* bpre  = (const float*)d_in[4];
    const float* Wih   = (const float*)d_in[5];
    const float* Whh   = (const float*)d_in[6];
    const float* bih   = (const float*)d_in[7];
    const float* bhh   = (const float*)d_in[8];
    const float* Wfc   = (const float*)d_in[9];
    const float* bfc   = (const float*)d_in[10];
    float* out = (float*)d_out;

    k_init<<<1024, 256>>>();
    k_pre <<<BATCH, TPB>>>(state, lng, lnb, Wpre, bpre);
    k_a0  <<<G4/8, 256>>>(Wih, bih, bhh);
    k_lstm<<<NCTA, TPB>>>(Wih, Whh, bih, bhh);
    k_fc  <<<TSTEPS, 256>>>(Wfc, bfc, out);
}

// round 12
// speedup vs baseline: 5.5840x; 1.1230x over previous
#include <cuda_runtime.h>
#include <math.h>

#define STATE_DIM 64
#define HID 512
#define ACT 8
#define BATCH 128
#define SEQ 16
#define TSTEPS (SEQ*BATCH)   // 2048 sequential LSTM steps
#define G4 (4*HID)
#define N0 64
#define N1 64
#define NCTA (N0+N1)
#define TPB 512
#define SENT 0x7FBFFFFFu     // NaN payload: impossible h / partial bit pattern
#define FULLM 0xffffffffu

// ---------------- scratch ---------------------------------------------------
__device__ float g_x [BATCH*HID];
__device__ float g_A0[BATCH*G4];
__device__ float g_h0[TSTEPS*HID];
__device__ float g_h1[TSTEPS*HID];

// ---------------- helpers ---------------------------------------------------
__device__ __forceinline__ float tanhapx(float x) {
    float y; asm("tanh.approx.f32 %0, %1;" : "=f"(y) : "f"(x)); return y;
}
__device__ __forceinline__ float sigf(float x) { return 0.5f*tanhapx(0.5f*x) + 0.5f; }

__device__ __forceinline__ unsigned ldvol32(const unsigned* p) {
    unsigned v;
    asm volatile("ld.volatile.global.u32 %0, [%1];" : "=r"(v) : "l"(p) : "memory");
    return v;
}
__device__ __forceinline__ uint2 ldvol64(const uint2* p) {
    uint2 v;
    asm volatile("ld.volatile.global.v2.u32 {%0,%1}, [%2];"
                 : "=r"(v.x), "=r"(v.y) : "l"(p) : "memory");
    return v;
}
__device__ __forceinline__ void stvolf(float* p, float v) {
    asm volatile("st.volatile.global.f32 [%0], %1;" :: "l"(p), "f"(v) : "memory");
}
__device__ __forceinline__ unsigned long long fma2(unsigned long long a,
                                                   unsigned long long b,
                                                   unsigned long long c) {
    unsigned long long d;
    asm("fma.rn.f32x2 %0, %1, %2, %3;" : "=l"(d) : "l"(a), "l"(b), "l"(c));
    return d;
}
__device__ __forceinline__ float fsum(unsigned long long v) {
    float x, y;
    asm("mov.b64 {%0,%1}, %2;" : "=f"(x), "=f"(y) : "l"(v));
    return x + y;
}

// ---------------- K0: sentinel-fill h histories (graph replays) -------------
__global__ void k_init() {
    unsigned i = blockIdx.x*blockDim.x + threadIdx.x;   // 1024*256 = 262144
    uint4 s = make_uint4(SENT, SENT, SENT, SENT);
    ((uint4*)g_h0)[i] = s;
    ((uint4*)g_h1)[i] = s;
}

// ---------------- K1: LayerNorm + pre-linear --------------------------------
__global__ void k_pre(const float* __restrict__ state, const float* __restrict__ lng,
                      const float* __restrict__ lnb,   const float* __restrict__ Wpre,
                      const float* __restrict__ bpre) {
    __shared__ float xn[STATE_DIM];
    __shared__ float stats[2];
    int b = blockIdx.x, tid = threadIdx.x;
    if (tid < STATE_DIM) xn[tid] = state[b*STATE_DIM + tid];
    __syncthreads();
    if (tid == 0) {
        float mu = 0.f;
        for (int k = 0; k < STATE_DIM; k++) mu += xn[k];
        mu *= (1.f/STATE_DIM);
        float var = 0.f;
        for (int k = 0; k < STATE_DIM; k++) { float d = xn[k]-mu; var += d*d; }
        var *= (1.f/STATE_DIM);
        stats[0] = mu; stats[1] = rsqrtf(var + 1e-5f);
    }
    __syncthreads();
    float mu = stats[0], rs = stats[1];
    if (tid < STATE_DIM) xn[tid] = (xn[tid]-mu)*rs*lng[tid] + lnb[tid];
    __syncthreads();
    float acc = bpre[tid];
    const float* w = Wpre + tid*STATE_DIM;
    #pragma unroll 16
    for (int k = 0; k < STATE_DIM; k++) acc = fmaf(w[k], xn[k], acc);
    g_x[b*HID + tid] = acc;
}

// ---------------- K2: A0 = W_ih0@x + b_ih0 + b_hh0 --------------------------
__global__ void k_a0(const float* __restrict__ Wih, const float* __restrict__ bih,
                     const float* __restrict__ bhh) {
    int tid = threadIdx.x, lane = tid & 31, warp = tid >> 5;
    int row = blockIdx.x*8 + warp;
    float wr[16];
    const float* w = Wih + (size_t)row*HID + lane*16;
    #pragma unroll
    for (int i = 0; i < 16; i++) wr[i] = w[i];
    float bsum = bih[row] + bhh[row];
    __shared__ float xs[HID];
    for (int b = 0; b < BATCH; b++) {
        __syncthreads();
        for (int i = tid; i < HID; i += 256) xs[i] = g_x[b*HID + i];
        __syncthreads();
        float a = 0.f;
        #pragma unroll
        for (int i = 0; i < 16; i++) a = fmaf(wr[i], xs[lane*16 + i], a);
        #pragma unroll
        for (int o = 16; o > 0; o >>= 1) a += __shfl_xor_sync(FULLM, a, o);
        if (lane == 0) g_A0[b*G4 + row] = a + bsum;
    }
}

// ---------------- K_LSTM: barrier-free interior, full/empty slots -----------
// Producer warps (1..15): global sentinel poll of own h slice -> FFMA2 ->
// WAIT slot EMPTY (SENT) -> volatile STS partial -> free-run into next step.
// Warp 0: own slice + FFMA, spin-sweep slots (volatile LDS), sum, cell with
// pre-shuffle activation, STG h, reset slots to SENT (marks empty).
// Parity double buffer + empty-gate bounds run-ahead to 2 steps; no bar.sync.
__global__ void __launch_bounds__(TPB, 1)
k_lstm(const float* __restrict__ Wih, const float* __restrict__ Whh,
       const float* __restrict__ bih, const float* __restrict__ bhh) {
    __shared__ float hbuf[2*HID];
    __shared__ unsigned redu[2][16][32];
    __shared__ float As[BATCH*32];
    __shared__ float bias1[32];
    const int tid = threadIdx.x, lane = tid & 31, warp = tid >> 5;
    const int j = lane & 7;
    float c_state = 0.f;

    if (blockIdx.x < N0) {
        // ===================== layer-0 group =====================
        const int g = blockIdx.x;
        const int grow = (lane>>3)*HID + g*8 + j;
        unsigned long long w2[16];                 // 32 cols [warp*32,+32)
        {
            const ulonglong2* wp = (const ulonglong2*)(Whh + (size_t)grow*HID + warp*32);
            #pragma unroll
            for (int i = 0; i < 8; i++) { ulonglong2 v = wp[i]; w2[2*i] = v.x; w2[2*i+1] = v.y; }
        }
        for (int i = tid; i < BATCH*32; i += TPB) {
            int bb = i >> 5, lr = i & 31;
            As[i] = g_A0[bb*G4 + (lr>>3)*HID + g*8 + (lr&7)];
        }
        for (int i = tid; i < 2*16*32; i += TPB) ((unsigned*)redu)[i] = SENT;
        __syncthreads();

        for (int t = 0; t < TSTEPS; t++) {
            const int par = t & 1;
            if (t > 0) {
                const unsigned* p =
                    (const unsigned*)(g_h0 + (size_t)(t-1)*HID + warp*32) + lane;
                unsigned v = ldvol32(p);
                while (!__all_sync(FULLM, v != SENT)) v = ldvol32(p);
                hbuf[warp*32 + lane] = __uint_as_float(v);
            } else {
                hbuf[warp*32 + lane] = 0.f;
            }
            __syncwarp();
            unsigned long long a0 = 0ull, a1 = 0ull;
            const ulonglong2* hp2 = (const ulonglong2*)(hbuf + warp*32);
            #pragma unroll
            for (int i = 0; i < 8; i++) {
                ulonglong2 v = hp2[i];
                a0 = fma2(w2[2*i],   v.x, a0);
                a1 = fma2(w2[2*i+1], v.y, a1);
            }
            float part = fsum(a0) + fsum(a1);
            if (warp != 0) {
                volatile unsigned* slot = &redu[par][warp][lane];
                unsigned e = *slot;                       // wait until EMPTY
                while (__any_sync(FULLM, e != SENT)) e = *slot;
                *slot = __float_as_uint(part);
            } else {
                float gv = part + As[(t & (BATCH-1))*32 + lane];
                unsigned vv[15];
                int bad;
                do {
                    bad = 0;
                    #pragma unroll
                    for (int w = 1; w < 16; w++) {
                        vv[w-1] = *(volatile unsigned*)&redu[par][w][lane];
                        bad |= (vv[w-1] == SENT);
                    }
                } while (__any_sync(FULLM, bad));
                float s0 = (__uint_as_float(vv[0]) + __uint_as_float(vv[1]))
                         + (__uint_as_float(vv[2]) + __uint_as_float(vv[3]));
                float s1 = (__uint_as_float(vv[4]) + __uint_as_float(vv[5]))
                         + (__uint_as_float(vv[6]) + __uint_as_float(vv[7]));
                float s2 = (__uint_as_float(vv[8]) + __uint_as_float(vv[9]))
                         + (__uint_as_float(vv[10]) + __uint_as_float(vv[11]));
                float s3 = (__uint_as_float(vv[12]) + __uint_as_float(vv[13]))
                         + __uint_as_float(vv[14]);
                gv += (s0 + s1) + (s2 + s3);
                float act = (lane >= 16 && lane < 24) ? tanhapx(gv) : sigf(gv);
                float vi = __shfl_sync(FULLM, act, j);
                float vf = __shfl_sync(FULLM, act, 8 + j);
                float vg = __shfl_sync(FULLM, act, 16 + j);
                float vo = __shfl_sync(FULLM, act, 24 + j);
                c_state = vf*c_state + vi*vg;
                float hv = vo*tanhapx(c_state);
                if (lane < 8) stvolf(g_h0 + (size_t)t*HID + g*8 + lane, hv);
                #pragma unroll
                for (int w = 1; w < 16; w++)
                    *(volatile unsigned*)&redu[par][w][lane] = SENT;   // mark empty
            }
        }
    } else {
        // ===================== layer-1 group =====================
        const int g = blockIdx.x - N0;
        const int grow = (lane>>3)*HID + g*8 + j;
        unsigned long long w2[32];                 // 64 cols [warp*64,+64) of [h0|h1]
        {
            const ulonglong2* wp = (warp < 8)
                ? (const ulonglong2*)(Wih + (size_t)G4*HID + (size_t)grow*HID + warp*64)
                : (const ulonglong2*)(Whh + (size_t)G4*HID + (size_t)grow*HID + (warp-8)*64);
            #pragma unroll
            for (int i = 0; i < 16; i++) { ulonglong2 v = wp[i]; w2[2*i] = v.x; w2[2*i+1] = v.y; }
        }
        if (tid < 32)
            bias1[tid] = bih[G4 + (tid>>3)*HID + g*8 + (tid&7)]
                       + bhh[G4 + (tid>>3)*HID + g*8 + (tid&7)];
        for (int i = tid; i < 2*16*32; i += TPB) ((unsigned*)redu)[i] = SENT;
        __syncthreads();

        for (int t = 0; t < TSTEPS; t++) {
            const int par = t & 1;
            if (warp < 8) {                        // h0[t]: produced ahead, cheap poll
                const uint2* p =
                    (const uint2*)(g_h0 + (size_t)t*HID + warp*64) + lane;
                uint2 v = ldvol64(p);
                while (!__all_sync(FULLM, (v.x != SENT) & (v.y != SENT)))
                    v = ldvol64(p);
                *(float2*)(hbuf + warp*64 + 2*lane) =
                    make_float2(__uint_as_float(v.x), __uint_as_float(v.y));
            } else if (t > 0) {                    // h1[t-1]: the recurrence
                const uint2* p =
                    (const uint2*)(g_h1 + (size_t)(t-1)*HID + (warp-8)*64) + lane;
                uint2 v = ldvol64(p);
                while (!__all_sync(FULLM, (v.x != SENT) & (v.y != SENT)))
                    v = ldvol64(p);
                *(float2*)(hbuf + warp*64 + 2*lane) =
                    make_float2(__uint_as_float(v.x), __uint_as_float(v.y));
            } else {
                *(float2*)(hbuf + warp*64 + 2*lane) = make_float2(0.f, 0.f);
            }
            __syncwarp();
            unsigned long long a0 = 0ull, a1 = 0ull, a2 = 0ull, a3 = 0ull;
            const ulonglong2* hp2 = (const ulonglong2*)(hbuf + warp*64);
            #pragma unroll
            for (int i = 0; i < 8; i++) {
                ulonglong2 v0 = hp2[2*i], v1 = hp2[2*i+1];
                a0 = fma2(w2[4*i],   v0.x, a0);
                a1 = fma2(w2[4*i+1], v0.y, a1);
                a2 = fma2(w2[4*i+2], v1.x, a2);
                a3 = fma2(w2[4*i+3], v1.y, a3);
            }
            float part = (fsum(a0) + fsum(a1)) + (fsum(a2) + fsum(a3));
            if (warp != 0) {
                volatile unsigned* slot = &redu[par][warp][lane];
                unsigned e = *slot;                       // wait until EMPTY
                while (__any_sync(FULLM, e != SENT)) e = *slot;
                *slot = __float_as_uint(part);
            } else {
                float gv = part + bias1[lane];
                unsigned vv[15];
                int bad;
                do {
                    bad = 0;
                    #pragma unroll
                    for (int w = 1; w < 16; w++) {
                        vv[w-1] = *(volatile unsigned*)&redu[par][w][lane];
                        bad |= (vv[w-1] == SENT);
                    }
                } while (__any_sync(FULLM, bad));
                float s0 = (__uint_as_float(vv[0]) + __uint_as_float(vv[1]))
                         + (__uint_as_float(vv[2]) + __uint_as_float(vv[3]));
                float s1 = (__uint_as_float(vv[4]) + __uint_as_float(vv[5]))
                         + (__uint_as_float(vv[6]) + __uint_as_float(vv[7]));
                float s2 = (__uint_as_float(vv[8]) + __uint_as_float(vv[9]))
                         + (__uint_as_float(vv[10]) + __uint_as_float(vv[11]));
                float s3 = (__uint_as_float(vv[12]) + __uint_as_float(vv[13]))
                         + __uint_as_float(vv[14]);
                gv += (s0 + s1) + (s2 + s3);
                float act = (lane >= 16 && lane < 24) ? tanhapx(gv) : sigf(gv);
                float vi = __shfl_sync(FULLM, act, j);
                float vf = __shfl_sync(FULLM, act, 8 + j);
                float vg = __shfl_sync(FULLM, act, 16 + j);
                float vo = __shfl_sync(FULLM, act, 24 + j);
                c_state = vf*c_state + vi*vg;
                float hv = vo*tanhapx(c_state);
                if (lane < 8) stvolf(g_h1 + (size_t)t*HID + g*8 + lane, hv);
                #pragma unroll
                for (int w = 1; w < 16; w++)
                    *(volatile unsigned*)&redu[par][w][lane] = SENT;   // mark empty
            }
        }
    }
}

// ---------------- K3: final FC + tanh ---------------------------------------
__global__ void k_fc(const float* __restrict__ Wfc, const float* __restrict__ bfc,
                     float* __restrict__ out) {
    int s = blockIdx.x;
    int tid = threadIdx.x, lane = tid & 31, a = tid >> 5;
    int tt = s >> 7, b = s & 127;
    const float* h = g_h1 + (size_t)s*HID;
    const float* w = Wfc + a*HID;
    float acc = 0.f;
    for (int k = lane; k < HID; k += 32) acc = fmaf(h[k], w[k], acc);
    #pragma unroll
    for (int o = 16; o > 0; o >>= 1) acc += __shfl_xor_sync(FULLM, acc, o);
    if (lane == 0) out[b*(SEQ*ACT) + tt*ACT + a] = tanhf(acc + bfc[a]);
}

// ---------------------------------------------------------------------------
extern "C" void kernel_launch(void* const* d_in, const int* in_sizes, int n_in,
                              void* d_out, int out_size) {
    const float* state = (const float*)d_in[0];
    const float* lng   = (const float*)d_in[1];
    const float* lnb   = (const float*)d_in[2];
    const float* Wpre  = (const float*)d_in[3];
    const float* bpre  = (const float*)d_in[4];
    const float* Wih   = (const float*)d_in[5];
    const float* Whh   = (const float*)d_in[6];
    const float* bih   = (const float*)d_in[7];
    const float* bhh   = (const float*)d_in[8];
    const float* Wfc   = (const float*)d_in[9];
    const float* bfc   = (const float*)d_in[10];
    float* out = (float*)d_out;

    k_init<<<1024, 256>>>();
    k_pre <<<BATCH, TPB>>>(state, lng, lnb, Wpre, bpre);
    k_a0  <<<G4/8, 256>>>(Wih, bih, bhh);
    k_lstm<<<NCTA, TPB>>>(Wih, Whh, bih, bhh);
    k_fc  <<<TSTEPS, 256>>>(Wfc, bfc, out);
}